// round 16
// baseline (speedup 1.0000x reference)
#include <cuda_runtime.h>
#include <cuda_bf16.h>
#include <cstdint>
#include <math.h>

#define BB 4
#define SS 1024
#define DD 1024
#define NH 16
#define DKH 64
#define BHN (BB*NH)   // 64
#define FST 72        // smem stride (bf16) for 64-wide tiles
#define SHF 4.0f      // constant softmax shift (cancels exactly in normalization)

typedef __nv_bfloat16 bf16;

// ---------------- device scratch ----------------
__device__ bf16  g_xb[BB*SS*DD];          // x in bf16
__device__ bf16  g_wqb[DD*DD], g_wkb[DD*DD], g_wvb[DD*DD], g_wob[DD*DD];
__device__ bf16  g_q[BB*NH*SS*DKH];       // [b,h,s,dk], q pre-scaled 0.125
__device__ bf16  g_k[BB*NH*SS*DKH];
__device__ bf16  g_v[BB*NH*SS*DKH];
__device__ bf16  g_vt[BB*NH*DKH*SS];      // V transposed per head: [bh][dk][s]
__device__ bf16  g_e[(size_t)BHN*SS*SS];  // unnormalized unbiased exp, bf16, 128MB
__device__ float g_lu[BHN*SS];            // unbiased row sums (shifted)
__device__ bf16  g_ctxb[BB*SS*DD];        // ctx in bf16
__device__ float g_res[BB*SS*DD];

// ---------------- helpers ----------------
__device__ __forceinline__ float warpSumT(float v){
    #pragma unroll
    for (int o=16;o;o>>=1) v += __shfl_xor_sync(0xffffffffu, v, o);
    return v;
}
__device__ __forceinline__ float blockSum(float v, float* sh){
    v = warpSumT(v);
    int w = threadIdx.x >> 5, l = threadIdx.x & 31;
    if (l == 0) sh[w] = v;
    __syncthreads();
    float r = sh[0];
    #pragma unroll
    for (int i=1;i<8;i++) r += sh[i];
    __syncthreads();
    return r;
}
__device__ __forceinline__ void mma_bf16(float* d, const uint32_t* a, const uint32_t* b){
    asm volatile(
        "mma.sync.aligned.m16n8k16.row.col.f32.bf16.bf16.f32 "
        "{%0,%1,%2,%3}, {%4,%5,%6,%7}, {%8,%9}, {%0,%1,%2,%3};\n"
        : "+f"(d[0]), "+f"(d[1]), "+f"(d[2]), "+f"(d[3])
        : "r"(a[0]), "r"(a[1]), "r"(a[2]), "r"(a[3]),
          "r"(b[0]), "r"(b[1]));
}
__device__ __forceinline__ void cpasync16(uint32_t s, const void* g){
    asm volatile("cp.async.cg.shared.global [%0], [%1], 16;\n" :: "r"(s), "l"(g));
}
__device__ __forceinline__ uint32_t smem_u32(const void* p){
    return (uint32_t)__cvta_generic_to_shared(p);
}
__device__ __forceinline__ uint32_t pack_bf16x2(float x, float y){
    __nv_bfloat162 a = __floats2bfloat162_rn(x, y);
    return *reinterpret_cast<uint32_t*>(&a);
}

// ---------------- fused fp32 -> bf16 convert for all 5 tensors ------------
__global__ void __launch_bounds__(256)
to_bf16_all(const float* __restrict__ x,
            const float* __restrict__ Wq, const float* __restrict__ Wk,
            const float* __restrict__ Wv, const float* __restrict__ Wo,
            bf16* __restrict__ xb, bf16* __restrict__ wqb, bf16* __restrict__ wkb,
            bf16* __restrict__ wvb, bf16* __restrict__ wob)
{
    int bidx = blockIdx.x;
    const float* src; bf16* dst; int base;
    if      (bidx < 4096){ src = x;  dst = xb;  base = bidx; }
    else if (bidx < 5120){ src = Wq; dst = wqb; base = bidx - 4096; }
    else if (bidx < 6144){ src = Wk; dst = wkb; base = bidx - 5120; }
    else if (bidx < 7168){ src = Wv; dst = wvb; base = bidx - 6144; }
    else                 { src = Wo; dst = wob; base = bidx - 7168; }
    int i = (base*256 + threadIdx.x)*4;
    float4 v = *(const float4*)(src + i);
    uint2 u;
    u.x = pack_bf16x2(v.x, v.y);
    u.y = pack_bf16x2(v.z, v.w);
    *(uint2*)(dst + i) = u;
}

// =====================================================================
// QKV merged GEMM, 256 threads (2x4 warps, 64x32 warp tiles).
// =====================================================================
__global__ void __launch_bounds__(256)
qkv_gemm(const bf16* __restrict__ A,
         const bf16* __restrict__ Wq, const bf16* __restrict__ Wk, const bf16* __restrict__ Wv,
         const float* __restrict__ bq, const float* __restrict__ bk, const float* __restrict__ bv,
         bf16* __restrict__ oq, bf16* __restrict__ ok, bf16* __restrict__ ov)
{
    constexpr int BK=32, SB=40;
    constexpr int MT=4, NTL=4;
    constexpr int Kd=1024;

    __shared__ bf16 As[2][128*SB];
    __shared__ bf16 Bs[2][128*SB];

    const int tid = threadIdx.x;
    const int wsel = blockIdx.x >> 3;
    const int bm0 = blockIdx.y*128, bn0 = (blockIdx.x & 7)*128;

    const bf16* Bg    = (wsel==0) ? Wq : (wsel==1) ? Wk : Wv;
    const float* bias = (wsel==0) ? bq : (wsel==1) ? bk : bv;
    bf16* C           = (wsel==0) ? oq : (wsel==1) ? ok : ov;
    const float scale = (wsel==0) ? 0.125f : 1.0f;

    auto loadA = [&](int buf, int k0){
        #pragma unroll
        for (int i = 0; i < 2; i++){
            int id = tid + (i << 8);
            int r = id >> 2, c8 = (id & 3) << 3;
            cpasync16(smem_u32(&As[buf][r*SB + c8]),
                      A + (size_t)(bm0 + r)*Kd + k0 + c8);
        }
    };
    auto loadB = [&](int buf, int k0){
        #pragma unroll
        for (int i = 0; i < 2; i++){
            int id = tid + (i << 8);
            int r = id >> 2, c8 = (id & 3) << 3;
            cpasync16(smem_u32(&Bs[buf][r*SB + c8]),
                      Bg + (size_t)(bn0 + r)*Kd + k0 + c8);
        }
    };

    const int lane = tid & 31, g = lane >> 2, tg = lane & 3;
    const int warp = tid >> 5;
    const int wm = (warp >> 2) * 64, wn = (warp & 3) * 32;

    float acc[MT][NTL][4];
    #pragma unroll
    for (int i=0;i<MT;i++)
        #pragma unroll
        for (int j=0;j<NTL;j++)
            #pragma unroll
            for (int r=0;r<4;r++) acc[i][j][r] = 0.f;

    loadA(0, 0); loadB(0, 0);
    asm volatile("cp.async.commit_group;\n");

    for (int it = 0; it < Kd/BK; it++){
        int buf = it & 1;
        if (it + 1 < Kd/BK) {
            loadA(buf^1, (it+1)*BK); loadB(buf^1, (it+1)*BK);
            asm volatile("cp.async.commit_group;\n");
            asm volatile("cp.async.wait_group 1;\n");
        } else {
            asm volatile("cp.async.wait_group 0;\n");
        }
        __syncthreads();

        #pragma unroll
        for (int kk = 0; kk < 2; kk++){
            uint32_t af[MT][4], bfr[NTL][2];
            #pragma unroll
            for (int i = 0; i < MT; i++){
                const bf16* ap = &As[buf][(wm + i*16 + g)*SB + kk*16 + 2*tg];
                af[i][0] = *(const uint32_t*)(ap);
                af[i][1] = *(const uint32_t*)(ap + 8*SB);
                af[i][2] = *(const uint32_t*)(ap + 8);
                af[i][3] = *(const uint32_t*)(ap + 8*SB + 8);
            }
            #pragma unroll
            for (int j = 0; j < NTL; j++){
                const bf16* bp = &Bs[buf][(wn + j*8 + g)*SB + kk*16 + 2*tg];
                bfr[j][0] = *(const uint32_t*)(bp);
                bfr[j][1] = *(const uint32_t*)(bp + 8);
            }
            #pragma unroll
            for (int i = 0; i < MT; i++)
                #pragma unroll
                for (int j = 0; j < NTL; j++)
                    mma_bf16(acc[i][j], af[i], bfr[j]);
        }
        __syncthreads();
    }

    #pragma unroll
    for (int i = 0; i < MT; i++){
        #pragma unroll
        for (int rr = 0; rr < 2; rr++){
            int row = bm0 + wm + i*16 + g + rr*8;
            #pragma unroll
            for (int j = 0; j < NTL; j++){
                int col = bn0 + wn + j*8 + 2*tg;
                float vx = (acc[i][j][rr*2+0] + bias[col])   * scale;
                float vy = (acc[i][j][rr*2+1] + bias[col+1]) * scale;
                int b = row >> 10, s = row & 1023;
                int h = col >> 6, dd = col & 63;
                uint32_t u = pack_bf16x2(vx, vy);
                *(uint32_t*)&C[((size_t)(b*NH + h) << 16) + s*DKH + dd] = u;
            }
        }
    }
}

// =====================================================================
// V transpose per head: g_v[bh][s][dk] -> g_vt[bh][dk][s]
// =====================================================================
__global__ void __launch_bounds__(256)
v_transpose(const bf16* __restrict__ V, bf16* __restrict__ Vt)
{
    __shared__ bf16 t[64][FST];
    const int sc = blockIdx.x, bh = blockIdx.y;
    const int tid = threadIdx.x;
    const bf16* src = V + ((size_t)bh << 16) + sc*64*DKH;

    #pragma unroll
    for (int i = 0; i < 2; i++){
        int id = tid + (i << 8);
        int r = id >> 3, c8 = (id & 7) << 3;
        *(uint4*)&t[r][c8] = *(const uint4*)(src + r*DKH + c8);
    }
    __syncthreads();

    bf16* dst = Vt + ((size_t)bh << 16) + sc*64;
    #pragma unroll
    for (int i = 0; i < 2; i++){
        int id = tid + (i << 8);
        int r = id >> 3, c8 = (id & 7) << 3;
        union { uint4 u; bf16 h[8]; } o;
        #pragma unroll
        for (int tj = 0; tj < 8; tj++) o.h[tj] = t[c8 + tj][r];
        *(uint4*)(dst + (size_t)r*SS + c8) = o.u;
    }
}

// =====================================================================
// FLASH: per (mtile=128, bh). S in regs, constant-shift softmax, P@V.
// ALSO stores unnormalized UNBIASED e=exp(s-SHF) (bf16) for out2.
// =====================================================================
__global__ void __launch_bounds__(256, 2)
flash_pv(const bf16* __restrict__ Q, const bf16* __restrict__ K,
         const bf16* __restrict__ Vt, bf16* __restrict__ ctx,
         bf16* __restrict__ eb, float* __restrict__ lu_out,
         const int* __restrict__ ts_ptr)
{
    extern __shared__ bf16 fsm[];
    bf16* Qs = fsm;                       // 128*FST
    bf16* Ks = fsm + 128*FST;             // 2*64*FST
    bf16* Vs = fsm + 128*FST + 2*64*FST;  // 2*64*FST

    const int tid = threadIdx.x;
    const int lane = tid & 31, g = lane >> 2, tg = lane & 3;
    const int w = tid >> 5;
    const int mt = blockIdx.x, bh = blockIdx.y;
    const int m0 = mt*128;

    const bf16* Qb = Q  + ((size_t)bh << 16) + (size_t)m0*DKH;
    const bf16* Kb = K  + ((size_t)bh << 16);
    const bf16* Vb = Vt + ((size_t)bh << 16);
    bf16* ebase = eb + ((size_t)bh << 20);

    #pragma unroll
    for (int i = 0; i < 4; i++){
        int id = tid + (i << 8);
        int r = id >> 3, c8 = (id & 7) << 3;
        cpasync16(smem_u32(&Qs[r*FST + c8]), Qb + r*DKH + c8);
    }
    auto loadK = [&](int buf, int k0){
        #pragma unroll
        for (int i = 0; i < 2; i++){
            int id = tid + (i << 8);
            int r = id >> 3, c8 = (id & 7) << 3;
            cpasync16(smem_u32(&Ks[buf*64*FST + r*FST + c8]),
                      Kb + (size_t)(k0 + r)*DKH + c8);
        }
    };
    auto loadV = [&](int buf, int k0){
        #pragma unroll
        for (int i = 0; i < 2; i++){
            int id = tid + (i << 8);
            int r = id >> 3, c8 = (id & 7) << 3;
            cpasync16(smem_u32(&Vs[buf*64*FST + r*FST + c8]),
                      Vb + (size_t)r*SS + k0 + c8);
        }
    };
    loadK(0, 0); loadV(0, 0);
    asm volatile("cp.async.commit_group;\n");

    float oacc[8][4];
    #pragma unroll
    for (int j=0;j<8;j++)
        #pragma unroll
        for (int v=0;v<4;v++) oacc[j][v]=0.f;
    float l0=0.f, l1=0.f, lu0=0.f, lu1=0.f;

    const bool dob = (ts_ptr[0] < 8) && (mt == 0) && (w < 4);
    const int row0 = m0 + w*16 + g, row1 = row0 + 8;

    uint32_t qf[4][4];
    bool qldd = false;

    for (int c = 0; c < 16; c++){
        int buf = c & 1;
        if (c + 1 < 16){
            loadK(buf^1, (c+1)*64); loadV(buf^1, (c+1)*64);
            asm volatile("cp.async.commit_group;\n");
            asm volatile("cp.async.wait_group 1;\n");
        } else {
            asm volatile("cp.async.wait_group 0;\n");
        }
        __syncthreads();

        if (!qldd){
            #pragma unroll
            for (int kk = 0; kk < 4; kk++){
                const bf16* ap = &Qs[(w*16 + g)*FST + kk*16 + 2*tg];
                qf[kk][0] = *(const uint32_t*)(ap);
                qf[kk][1] = *(const uint32_t*)(ap + 8*FST);
                qf[kk][2] = *(const uint32_t*)(ap + 8);
                qf[kk][3] = *(const uint32_t*)(ap + 8*FST + 8);
            }
            qldd = true;
        }

        const bf16* Kc = Ks + buf*64*FST;
        const bf16* Vc = Vs + buf*64*FST;

        float sacc[8][4];
        #pragma unroll
        for (int j=0;j<8;j++)
            #pragma unroll
            for (int v=0;v<4;v++) sacc[j][v]=0.f;

        #pragma unroll
        for (int kk = 0; kk < 4; kk++){
            #pragma unroll
            for (int j = 0; j < 8; j++){
                const bf16* bp = &Kc[(j*8 + g)*FST + kk*16 + 2*tg];
                uint32_t bfr[2] = { *(const uint32_t*)(bp), *(const uint32_t*)(bp + 8) };
                mma_bf16(sacc[j], qf[kk], bfr);
            }
        }

        const bool bchunk = dob && (c == 0);
        if (bchunk){
            // unbiased exps: sum into lu AND store to e-buffer
            float u0=0.f, u1=0.f;
            #pragma unroll
            for (int j = 0; j < 8; j++){
                float e00 = __expf(sacc[j][0]-SHF), e01 = __expf(sacc[j][1]-SHF);
                float e10 = __expf(sacc[j][2]-SHF), e11 = __expf(sacc[j][3]-SHF);
                u0 += e00 + e01; u1 += e10 + e11;
                int col = j*8 + 2*tg;
                *(uint32_t*)&ebase[(size_t)row0*SS + col] = pack_bf16x2(e00, e01);
                *(uint32_t*)&ebase[(size_t)row1*SS + col] = pack_bf16x2(e10, e11);
            }
            lu0 += u0; lu1 += u1;
            #pragma unroll
            for (int j = 0; j < 8; j++){
                int col = j*8 + 2*tg;
                sacc[j][0] += 0.1f / (fabsf((float)(row0 - col))     + 1.0f);
                sacc[j][1] += 0.1f / (fabsf((float)(row0 - col - 1)) + 1.0f);
                sacc[j][2] += 0.1f / (fabsf((float)(row1 - col))     + 1.0f);
                sacc[j][3] += 0.1f / (fabsf((float)(row1 - col - 1)) + 1.0f);
            }
        }

        // exp -> pack -> PV MMA interleaved per kk; store e when unbiased
        float r0 = 0.f, r1 = 0.f;
        #pragma unroll
        for (int kk = 0; kk < 4; kk++){
            const int j0 = 2*kk, j1 = 2*kk + 1;
            float p00 = __expf(sacc[j0][0]-SHF), p01 = __expf(sacc[j0][1]-SHF);
            float p02 = __expf(sacc[j0][2]-SHF), p03 = __expf(sacc[j0][3]-SHF);
            float p10 = __expf(sacc[j1][0]-SHF), p11 = __expf(sacc[j1][1]-SHF);
            float p12 = __expf(sacc[j1][2]-SHF), p13 = __expf(sacc[j1][3]-SHF);
            r0 += p00 + p01 + p10 + p11;
            r1 += p02 + p03 + p12 + p13;
            uint32_t a[4];
            a[0] = pack_bf16x2(p00, p01);
            a[1] = pack_bf16x2(p02, p03);
            a[2] = pack_bf16x2(p10, p11);
            a[3] = pack_bf16x2(p12, p13);
            if (!bchunk){
                int col0 = c*64 + j0*8 + 2*tg;
                int col1 = c*64 + j1*8 + 2*tg;
                *(uint32_t*)&ebase[(size_t)row0*SS + col0] = a[0];
                *(uint32_t*)&ebase[(size_t)row1*SS + col0] = a[1];
                *(uint32_t*)&ebase[(size_t)row0*SS + col1] = a[2];
                *(uint32_t*)&ebase[(size_t)row1*SS + col1] = a[3];
            }
            #pragma unroll
            for (int j = 0; j < 8; j++){
                const bf16* bp = &Vc[(j*8 + g)*FST + kk*16 + 2*tg];
                uint32_t b2[2] = { *(const uint32_t*)(bp), *(const uint32_t*)(bp + 8) };
                mma_bf16(oacc[j], a, b2);
            }
        }
        l0 += r0; l1 += r1;
        if (!bchunk){ lu0 += r0; lu1 += r1; }
        __syncthreads();
    }

    #pragma unroll
    for (int o = 1; o < 4; o <<= 1){
        l0  += __shfl_xor_sync(0xffffffffu, l0,  o);
        l1  += __shfl_xor_sync(0xffffffffu, l1,  o);
        lu0 += __shfl_xor_sync(0xffffffffu, lu0, o);
        lu1 += __shfl_xor_sync(0xffffffffu, lu1, o);
    }
    float i0 = 1.0f / l0, i1 = 1.0f / l1;

    bf16* cb = ctx + ((size_t)(bh >> 4) << 20) + (size_t)(bh & 15)*64;
    #pragma unroll
    for (int j = 0; j < 8; j++){
        int col = j*8 + 2*tg;
        *(uint32_t*)&cb[(size_t)row0*DD + col] = pack_bf16x2(oacc[j][0]*i0, oacc[j][1]*i0);
        *(uint32_t*)&cb[(size_t)row1*DD + col] = pack_bf16x2(oacc[j][2]*i1, oacc[j][3]*i1);
    }
    if (tg == 0){
        lu_out[bh*SS + row0] = lu0;
        lu_out[bh*SS + row1] = lu1;
    }
}

// =====================================================================
// FUSED TAIL: blocks [0,4096) = out2 reduce (e/lu head-mean, mem-bound);
// blocks [4096,4352) = out-projection GEMM.
// =====================================================================
__global__ void __launch_bounds__(256, 2)
tail_fused(const bf16* __restrict__ eb, const float* __restrict__ lu,
           float* __restrict__ out2,
           const bf16* __restrict__ ctxb, const bf16* __restrict__ Wob,
           const float* __restrict__ bo, const float* __restrict__ xresid,
           float* __restrict__ res)
{
    extern __shared__ char tsm[];
    const int tid = threadIdx.x;

    if (blockIdx.x < 4096){
        // ---------------- out2 reduce ----------------
        int id = blockIdx.x*256 + tid;
        int col4 = (id & 255) * 4;
        int row  = (id >> 8) & 1023;
        int b    = id >> 18;

        float4 acc = make_float4(0.f, 0.f, 0.f, 0.f);
        #pragma unroll 1
        for (int h = 0; h < NH; h++){
            int bh = b*NH + h;
            uint2 u = *(const uint2*)(eb + ((size_t)bh << 20) + ((size_t)row << 10) + col4);
            __nv_bfloat162 lo = *reinterpret_cast<__nv_bfloat162*>(&u.x);
            __nv_bfloat162 hi = *reinterpret_cast<__nv_bfloat162*>(&u.y);
            float inv = 1.0f / lu[bh*SS + row];
            acc.x += __bfloat162float(lo.x)*inv;
            acc.y += __bfloat162float(lo.y)*inv;
            acc.z += __bfloat162float(hi.x)*inv;
            acc.w += __bfloat162float(hi.y)*inv;
        }
        const float k16 = 1.0f/16.0f;
        *(float4*)&out2[(((size_t)(b*SS + row)) << 10) + col4] =
            make_float4(acc.x*k16, acc.y*k16, acc.z*k16, acc.w*k16);
    } else {
        // ---------------- out-projection (256 threads, 2x4 warps) ----------
        constexpr int BK=32, SB=40, Kd=1024;
        bf16* As = (bf16*)tsm;                 // [2][128*SB]
        bf16* Bs = (bf16*)tsm + 2*128*SB;      // [2][128*SB]

        const int lane = tid & 31, g = lane >> 2, tg = lane & 3;
        const int w = tid >> 5;
        const int blk = blockIdx.x - 4096;
        const int bm0 = (blk >> 3)*128, bn0 = (blk & 7)*128;

        auto loadA = [&](int buf, int k0){
            #pragma unroll
            for (int i = 0; i < 2; i++){
                int id = tid + (i << 8);
                int r = id >> 2, c8 = (id & 3) << 3;
                cpasync16(smem_u32(&As[buf*128*SB + r*SB + c8]),
                          ctxb + (size_t)(bm0 + r)*Kd + k0 + c8);
            }
        };
        auto loadB = [&](int buf, int k0){
            #pragma unroll
            for (int i = 0; i < 2; i++){
                int id = tid + (i << 8);
                int r = id >> 2, c8 = (id & 3) << 3;
                cpasync16(smem_u32(&Bs[buf*128*SB + r*SB + c8]),
                          Wob + (size_t)(bn0 + r)*Kd + k0 + c8);
            }
        };

        const int wm = (w >> 2) * 64, wn = (w & 3) * 32;

        float acc[4][4][4];
        #pragma unroll
        for (int i=0;i<4;i++)
            #pragma unroll
            for (int j=0;j<4;j++)
                #pragma unroll
                for (int r=0;r<4;r++) acc[i][j][r] = 0.f;

        loadA(0, 0); loadB(0, 0);
        asm volatile("cp.async.commit_group;\n");

        for (int it = 0; it < Kd/BK; it++){
            int buf = it & 1;
            if (it + 1 < Kd/BK) {
                loadA(buf^1, (it+1)*BK); loadB(buf^1, (it+1)*BK);
                asm volatile("cp.async.commit_group;\n");
                asm volatile("cp.async.wait_group 1;\n");
            } else {
                asm volatile("cp.async.wait_group 0;\n");
            }
            __syncthreads();

            #pragma unroll
            for (int kk = 0; kk < 2; kk++){
                uint32_t af[4][4], bfr[4][2];
                #pragma unroll
                for (int i = 0; i < 4; i++){
                    const bf16* ap = &As[buf*128*SB + (wm + i*16 + g)*SB + kk*16 + 2*tg];
                    af[i][0] = *(const uint32_t*)(ap);
                    af[i][1] = *(const uint32_t*)(ap + 8*SB);
                    af[i][2] = *(const uint32_t*)(ap + 8);
                    af[i][3] = *(const uint32_t*)(ap + 8*SB + 8);
                }
                #pragma unroll
                for (int j = 0; j < 4; j++){
                    const bf16* bp = &Bs[buf*128*SB + (wn + j*8 + g)*SB + kk*16 + 2*tg];
                    bfr[j][0] = *(const uint32_t*)(bp);
                    bfr[j][1] = *(const uint32_t*)(bp + 8);
                }
                #pragma unroll
                for (int i = 0; i < 4; i++)
                    #pragma unroll
                    for (int j = 0; j < 4; j++)
                        mma_bf16(acc[i][j], af[i], bfr[j]);
            }
            __syncthreads();
        }

        #pragma unroll
        for (int i = 0; i < 4; i++){
            #pragma unroll
            for (int rr = 0; rr < 2; rr++){
                int row = bm0 + wm + i*16 + g + rr*8;
                #pragma unroll
                for (int j = 0; j < 4; j++){
                    int col = bn0 + wn + j*8 + 2*tg;
                    size_t idx = (size_t)row*DD + col;
                    float2 r2 = *(const float2*)&xresid[idx];
                    float2 o = make_float2(acc[i][j][rr*2+0] + bo[col]   + r2.x,
                                           acc[i][j][rr*2+1] + bo[col+1] + r2.y);
                    *(float2*)&res[idx] = o;
                }
            }
        }
    }
}

// ---------------- LayerNorm --------------------------------------------------
__global__ void __launch_bounds__(256)
layernorm(const float* __restrict__ R, const float* __restrict__ gamma,
          const float* __restrict__ beta, float* __restrict__ out)
{
    __shared__ float red[8];
    int row = blockIdx.x;
    int tid = threadIdx.x;
    const float* src = R + ((size_t)row << 10);
    float v[4];
    #pragma unroll
    for (int j=0;j<4;j++) v[j] = src[tid + (j<<8)];
    float s = v[0]+v[1]+v[2]+v[3];
    s = blockSum(s, red);
    float mu = s * (1.0f/1024.0f);
    float q = 0.f;
    #pragma unroll
    for (int j=0;j<4;j++) { float d = v[j]-mu; q += d*d; }
    q = blockSum(q, red);
    float inv = rsqrtf(q * (1.0f/1024.0f) + 1e-5f);
    #pragma unroll
    for (int j=0;j<4;j++) {
        int c = tid + (j<<8);
        out[((size_t)row << 10) + c] = (v[j]-mu)*inv*gamma[c] + beta[c];
    }
}

// ---------------- launch -----------------------------------------------------
extern "C" void kernel_launch(void* const* d_in, const int* in_sizes, int n_in,
                              void* d_out, int out_size)
{
    const float* x  = (const float*)d_in[0];
    const int*   ts = (const int*)  d_in[1];
    const float* Wq = (const float*)d_in[2];
    const float* bq = (const float*)d_in[3];
    const float* Wk = (const float*)d_in[4];
    const float* bk = (const float*)d_in[5];
    const float* Wv = (const float*)d_in[6];
    const float* bv = (const float*)d_in[7];
    const float* Wo = (const float*)d_in[8];
    const float* bo = (const float*)d_in[9];
    const float* ga = (const float*)d_in[10];
    const float* be = (const float*)d_in[11];

    float* out1 = (float*)d_out;
    float* out2 = out1 + (size_t)BB*SS*DD;

    void *pxb, *pwq, *pwk, *pwv, *pwo, *pq, *pk, *pv, *pvt, *pe, *plu, *pctxb, *pres;
    cudaGetSymbolAddress(&pxb, g_xb);
    cudaGetSymbolAddress(&pwq, g_wqb);
    cudaGetSymbolAddress(&pwk, g_wkb);
    cudaGetSymbolAddress(&pwv, g_wvb);
    cudaGetSymbolAddress(&pwo, g_wob);
    cudaGetSymbolAddress(&pq,  g_q);
    cudaGetSymbolAddress(&pk,  g_k);
    cudaGetSymbolAddress(&pv,  g_v);
    cudaGetSymbolAddress(&pvt, g_vt);
    cudaGetSymbolAddress(&pe,  g_e);
    cudaGetSymbolAddress(&plu, g_lu);
    cudaGetSymbolAddress(&pctxb, g_ctxb);
    cudaGetSymbolAddress(&pres,g_res);

    const int SM_FLSH = (128 + 2*64 + 2*64)*FST*2;        // 55296 B
    const int SM_TAIL = 4*128*40*2;                       // 40960 B
    cudaFuncSetAttribute((const void*)flash_pv,   cudaFuncAttributeMaxDynamicSharedMemorySize, SM_FLSH);
    cudaFuncSetAttribute((const void*)tail_fused, cudaFuncAttributeMaxDynamicSharedMemorySize, SM_TAIL);

    // fused bf16 conversion: x + 4 weight matrices, one launch
    to_bf16_all<<<8192, 256>>>(x, Wq, Wk, Wv, Wo,
                               (bf16*)pxb, (bf16*)pwq, (bf16*)pwk, (bf16*)pwv, (bf16*)pwo);

    // QKV projections (bf16 MMA, 256 threads) -> bf16 head layout
    qkv_gemm<<<dim3(24,32), 256>>>((const bf16*)pxb,
                                   (const bf16*)pwq, (const bf16*)pwk, (const bf16*)pwv,
                                   bq, bk, bv,
                                   (bf16*)pq, (bf16*)pk, (bf16*)pv);

    // V transpose
    v_transpose<<<dim3(16,BHN), 256>>>((const bf16*)pv, (bf16*)pvt);

    // Flash attention: ctx (bf16) + e-buffer + unbiased row sums
    flash_pv<<<dim3(8,BHN), 256, SM_FLSH>>>((const bf16*)pq, (const bf16*)pk,
                                            (const bf16*)pvt, (bf16*)pctxb,
                                            (bf16*)pe, (float*)plu, ts);

    // Fused tail: out2 reduce (blocks 0-4095) + out-projection (4096-4351)
    tail_fused<<<4352, 256, SM_TAIL>>>((const bf16*)pe, (const float*)plu, out2,
                                       (const bf16*)pctxb, (const bf16*)pwo,
                                       bo, x, (float*)pres);

    // LayerNorm -> output 1
    layernorm<<<dim3(BB*SS), 256>>>((const float*)pres, ga, be, out1);
}